// round 7
// baseline (speedup 1.0000x reference)
#include <cuda_runtime.h>

#define D_MODEL 1024
#define INTER   1024
#define N_EXP   8
#define T_TOK   8192
#define MAX_TILES 208
#define MAX_ROWS  (MAX_TILES * 128)   // 26624

// ---------------- scratch (device globals: allocation-free) ----------------
__device__ float g_h [MAX_ROWS * INTER];    // SwiGLU hidden per slot
__device__ float g_c2[MAX_ROWS * D_MODEL];  // per-slot expert output
__device__ int   g_srcTok[MAX_ROWS];        // slot -> token (-1 = padding)
__device__ int   g_eid [T_TOK * 2];         // (t,k) -> expert id
__device__ float g_wgt [T_TOK * 2];         // (t,k) -> routing weight
__device__ int   g_slot[T_TOK * 2];         // (t,k) -> slot position
__device__ int   g_tileExpert[MAX_TILES];   // row-tile -> expert (8 = shared)
__device__ int   g_nTiles;
__device__ int   g_sharedBase;

// ---------------- 1) gate: logits -> softmax -> top-2 ----------------
__global__ void gate_kernel(const float* __restrict__ x, const float* __restrict__ gw) {
    int warp = threadIdx.x >> 5, lane = threadIdx.x & 31;
    int t = blockIdx.x * 4 + warp;
    const float* xr = x + (size_t)t * D_MODEL;
    float xa[32];
#pragma unroll
    for (int i = 0; i < 32; i++) xa[i] = xr[lane + i * 32];
    float p[8];
#pragma unroll
    for (int e = 0; e < 8; e++) {
        const float* w = gw + e * D_MODEL;
        float s = 0.f;
#pragma unroll
        for (int i = 0; i < 32; i++) s += xa[i] * w[lane + i * 32];
#pragma unroll
        for (int off = 16; off > 0; off >>= 1) s += __shfl_xor_sync(0xffffffffu, s, off);
        p[e] = s;
    }
    float m = p[0];
#pragma unroll
    for (int e = 1; e < 8; e++) m = fmaxf(m, p[e]);
    float den = 0.f;
#pragma unroll
    for (int e = 0; e < 8; e++) { p[e] = __expf(p[e] - m); den += p[e]; }
    float inv = 1.f / den;
#pragma unroll
    for (int e = 0; e < 8; e++) p[e] *= inv;
    // top-2, first occurrence on ties (matches lax.top_k)
    int i0 = 0;
#pragma unroll
    for (int e = 1; e < 8; e++) if (p[e] > p[i0]) i0 = e;
    int i1 = -1; float v1 = -1.f;
#pragma unroll
    for (int e = 0; e < 8; e++) if (e != i0 && p[e] > v1) { v1 = p[e]; i1 = e; }
    if (lane == 0) {
        g_eid[2 * t]     = i0; g_wgt[2 * t]     = p[i0];
        g_eid[2 * t + 1] = i1; g_wgt[2 * t + 1] = v1;
    }
}

// ---------------- 2) deterministic stable counting sort into expert regions ----------------
__global__ void route_build() {
    __shared__ int warpsum[32][8];
    __shared__ int sExpBase[9];
    __shared__ int sExpCnt[8];
    int tid = threadIdx.x, lane = tid & 31, wid = tid >> 5;

    int lc[8];
#pragma unroll
    for (int e = 0; e < 8; e++) lc[e] = 0;
    int base = tid * 16;
    int eids[16];
#pragma unroll
    for (int j = 0; j < 16; j++) { int e = g_eid[base + j]; eids[j] = e; lc[e]++; }

    int incl[8];
#pragma unroll
    for (int e = 0; e < 8; e++) {
        int v = lc[e];
#pragma unroll
        for (int o = 1; o < 32; o <<= 1) {
            int n = __shfl_up_sync(0xffffffffu, v, o);
            if (lane >= o) v += n;
        }
        incl[e] = v;
        if (lane == 31) warpsum[wid][e] = v;
    }
    __syncthreads();
    if (tid < 256) {                 // scan warp totals: warp tid>>5 handles expert e
        int e = tid >> 5, l = tid & 31;
        int v = warpsum[l][e];
#pragma unroll
        for (int o = 1; o < 32; o <<= 1) {
            int n = __shfl_up_sync(0xffffffffu, v, o);
            if (l >= o) v += n;
        }
        warpsum[l][e] = v;           // inclusive across warps
    }
    __syncthreads();
    if (tid == 0) {
        int off = 0, nt = 0;
        for (int e = 0; e < 8; e++) {
            int c = warpsum[31][e];
            sExpBase[e] = off; sExpCnt[e] = c;
            int tiles = (c + 127) >> 7;
            for (int j = 0; j < tiles; j++) g_tileExpert[nt++] = e;
            off += tiles << 7;
        }
        sExpBase[8] = off;
        for (int j = 0; j < 64; j++) g_tileExpert[nt++] = 8;  // shared: 8192 rows = 64 tiles
        g_nTiles = nt;
        g_sharedBase = off;
    }
    __syncthreads();

    int run[8];
#pragma unroll
    for (int e = 0; e < 8; e++) {
        int pw = (wid == 0) ? 0 : warpsum[wid - 1][e];
        run[e] = sExpBase[e] + pw + (incl[e] - lc[e]);
    }
#pragma unroll
    for (int j = 0; j < 16; j++) {
        int e = eids[j];
        int pos = run[e]++;
        g_srcTok[pos] = (base + j) >> 1;   // token id
        g_slot[base + j] = pos;
    }
    // padding rows
    for (int e = 0; e < 8; e++) {
        int s = sExpBase[e] + sExpCnt[e], en = sExpBase[e + 1];
        for (int p = s + tid; p < en; p += 1024) g_srcTok[p] = -1;
    }
    int sb = sExpBase[8];
    for (int t = tid; t < T_TOK; t += 1024) g_srcTok[sb + t] = t;
}

// ---------------- 3) fused gather-GEMM: h = silu(Xg@W1+b1) * (Xg@W3+b3) ----------------
// tile 128(M) x 64(N) x 16(K), 256 threads, thread tile 8x4, dual accumulators
__global__ __launch_bounds__(256, 2) void gemm_h(
    const float* __restrict__ x,
    const float* __restrict__ w1, const float* __restrict__ b1,
    const float* __restrict__ w3, const float* __restrict__ b3,
    const float* __restrict__ sw1, const float* __restrict__ sb1,
    const float* __restrict__ sw3, const float* __restrict__ sb3)
{
    int tileId = blockIdx.y;
    if (tileId >= g_nTiles) return;
    int e = g_tileExpert[tileId];
    int rowBase = tileId << 7;
    int n0 = blockIdx.x << 6;
    const float* B1  = (e < N_EXP) ? (w1 + (size_t)e * D_MODEL * INTER) : sw1;
    const float* B3  = (e < N_EXP) ? (w3 + (size_t)e * D_MODEL * INTER) : sw3;
    const float* bi1 = (e < N_EXP) ? (b1 + e * INTER) : sb1;
    const float* bi3 = (e < N_EXP) ? (b3 + e * INTER) : sb3;

    __shared__ float As[16][128];
    __shared__ float Bg[16][64];
    __shared__ float Bu[16][64];

    int tid = threadIdx.x;
    int tx = tid & 15, ty = tid >> 4;
    int ra0 = tid >> 2, seg = tid & 3;
    int ra1 = ra0 + 64;
    int tok0 = g_srcTok[rowBase + ra0];
    int tok1 = g_srcTok[rowBase + ra1];
    const float* ap0 = x + (size_t)max(tok0, 0) * D_MODEL + seg * 4;
    const float* ap1 = x + (size_t)max(tok1, 0) * D_MODEL + seg * 4;
    int bk = tid >> 4, bn4 = tid & 15;
    const float* bp1 = B1 + (size_t)bk * INTER + n0 + bn4 * 4;
    const float* bp3 = B3 + (size_t)bk * INTER + n0 + bn4 * 4;

    float accg[8][4], accu[8][4];
#pragma unroll
    for (int i = 0; i < 8; i++)
#pragma unroll
        for (int j = 0; j < 4; j++) { accg[i][j] = 0.f; accu[i][j] = 0.f; }

    float4 a0 = make_float4(0.f, 0.f, 0.f, 0.f), a1 = a0, gv4, uv4;
    if (tok0 >= 0) a0 = *(const float4*)ap0;
    if (tok1 >= 0) a1 = *(const float4*)ap1;
    gv4 = *(const float4*)bp1;
    uv4 = *(const float4*)bp3;

    for (int kt = 0; kt < 64; kt++) {
        __syncthreads();
        As[seg * 4 + 0][ra0] = a0.x; As[seg * 4 + 1][ra0] = a0.y;
        As[seg * 4 + 2][ra0] = a0.z; As[seg * 4 + 3][ra0] = a0.w;
        As[seg * 4 + 0][ra1] = a1.x; As[seg * 4 + 1][ra1] = a1.y;
        As[seg * 4 + 2][ra1] = a1.z; As[seg * 4 + 3][ra1] = a1.w;
        *(float4*)&Bg[bk][bn4 * 4] = gv4;
        *(float4*)&Bu[bk][bn4 * 4] = uv4;
        __syncthreads();
        if (kt < 63) {  // register prefetch of next K-tile overlaps compute below
            int koff = (kt + 1) << 4;
            a0 = make_float4(0.f, 0.f, 0.f, 0.f); a1 = a0;
            if (tok0 >= 0) a0 = *(const float4*)(ap0 + koff);
            if (tok1 >= 0) a1 = *(const float4*)(ap1 + koff);
            gv4 = *(const float4*)(bp1 + (size_t)(kt + 1) * 16 * INTER);
            uv4 = *(const float4*)(bp3 + (size_t)(kt + 1) * 16 * INTER);
        }
#pragma unroll
        for (int k = 0; k < 16; k++) {
            float4 af0 = *(const float4*)&As[k][ty * 8];
            float4 af1 = *(const float4*)&As[k][ty * 8 + 4];
            float4 bgv = *(const float4*)&Bg[k][tx * 4];
            float4 buv = *(const float4*)&Bu[k][tx * 4];
            float ar[8] = {af0.x, af0.y, af0.z, af0.w, af1.x, af1.y, af1.z, af1.w};
            float bg[4] = {bgv.x, bgv.y, bgv.z, bgv.w};
            float bu[4] = {buv.x, buv.y, buv.z, buv.w};
#pragma unroll
            for (int i = 0; i < 8; i++) {
#pragma unroll
                for (int j = 0; j < 4; j++) {
                    accg[i][j] = fmaf(ar[i], bg[j], accg[i][j]);
                    accu[i][j] = fmaf(ar[i], bu[j], accu[i][j]);
                }
            }
        }
    }
    float bg4[4], bu4[4];
#pragma unroll
    for (int j = 0; j < 4; j++) {
        bg4[j] = bi1[n0 + tx * 4 + j];
        bu4[j] = bi3[n0 + tx * 4 + j];
    }
#pragma unroll
    for (int i = 0; i < 8; i++) {
        float4 hv;
        float* hp = &hv.x;
#pragma unroll
        for (int j = 0; j < 4; j++) {
            float g = accg[i][j] + bg4[j];
            float u = accu[i][j] + bu4[j];
            hp[j] = g / (1.f + __expf(-g)) * u;   // silu(g) * u
        }
        int row = rowBase + ty * 8 + i;
        *(float4*)&g_h[(size_t)row * INTER + n0 + tx * 4] = hv;
    }
}

// ---------------- 4) GEMM2: C2 = H @ W2 + b2 (contiguous rows) ----------------
__global__ __launch_bounds__(256, 2) void gemm_c2(
    const float* __restrict__ w2, const float* __restrict__ b2,
    const float* __restrict__ sw2, const float* __restrict__ sb2)
{
    int tileId = blockIdx.y;
    if (tileId >= g_nTiles) return;
    int e = g_tileExpert[tileId];
    int rowBase = tileId << 7;
    int n0 = blockIdx.x << 6;
    const float* B2  = (e < N_EXP) ? (w2 + (size_t)e * INTER * D_MODEL) : sw2;
    const float* bi2 = (e < N_EXP) ? (b2 + e * D_MODEL) : sb2;

    __shared__ float As[16][128];
    __shared__ float Bs[16][64];

    int tid = threadIdx.x;
    int tx = tid & 15, ty = tid >> 4;
    int ra0 = tid >> 2, seg = tid & 3;
    int ra1 = ra0 + 64;
    const float* ap0 = g_h + (size_t)(rowBase + ra0) * INTER + seg * 4;
    const float* ap1 = g_h + (size_t)(rowBase + ra1) * INTER + seg * 4;
    int bk = tid >> 4, bn4 = tid & 15;
    const float* bp = B2 + (size_t)bk * D_MODEL + n0 + bn4 * 4;

    float acc[8][4];
#pragma unroll
    for (int i = 0; i < 8; i++)
#pragma unroll
        for (int j = 0; j < 4; j++) acc[i][j] = 0.f;

    float4 a0 = *(const float4*)ap0;
    float4 a1 = *(const float4*)ap1;
    float4 bv = *(const float4*)bp;

    for (int kt = 0; kt < 64; kt++) {
        __syncthreads();
        As[seg * 4 + 0][ra0] = a0.x; As[seg * 4 + 1][ra0] = a0.y;
        As[seg * 4 + 2][ra0] = a0.z; As[seg * 4 + 3][ra0] = a0.w;
        As[seg * 4 + 0][ra1] = a1.x; As[seg * 4 + 1][ra1] = a1.y;
        As[seg * 4 + 2][ra1] = a1.z; As[seg * 4 + 3][ra1] = a1.w;
        *(float4*)&Bs[bk][bn4 * 4] = bv;
        __syncthreads();
        if (kt < 63) {
            int koff = (kt + 1) << 4;
            a0 = *(const float4*)(ap0 + koff);
            a1 = *(const float4*)(ap1 + koff);
            bv = *(const float4*)(bp + (size_t)(kt + 1) * 16 * D_MODEL);
        }
#pragma unroll
        for (int k = 0; k < 16; k++) {
            float4 af0 = *(const float4*)&As[k][ty * 8];
            float4 af1 = *(const float4*)&As[k][ty * 8 + 4];
            float4 bsv = *(const float4*)&Bs[k][tx * 4];
            float ar[8] = {af0.x, af0.y, af0.z, af0.w, af1.x, af1.y, af1.z, af1.w};
            float bb[4] = {bsv.x, bsv.y, bsv.z, bsv.w};
#pragma unroll
            for (int i = 0; i < 8; i++) {
#pragma unroll
                for (int j = 0; j < 4; j++)
                    acc[i][j] = fmaf(ar[i], bb[j], acc[i][j]);
            }
        }
    }
    float bb[4];
#pragma unroll
    for (int j = 0; j < 4; j++) bb[j] = bi2[n0 + tx * 4 + j];
#pragma unroll
    for (int i = 0; i < 8; i++) {
        float4 ov;
        ov.x = acc[i][0] + bb[0]; ov.y = acc[i][1] + bb[1];
        ov.z = acc[i][2] + bb[2]; ov.w = acc[i][3] + bb[3];
        int row = rowBase + ty * 8 + i;
        *(float4*)&g_c2[(size_t)row * D_MODEL + n0 + tx * 4] = ov;
    }
}

// ---------------- 5) combine: out[t] = w0*C2[s0] + w1*C2[s1] + C2[shared_t] ----------------
__global__ void combine_kernel(float* __restrict__ out) {
    int t = blockIdx.x;
    int d4 = threadIdx.x;  // 256 float4 per row
    int s0 = g_slot[2 * t], s1 = g_slot[2 * t + 1];
    float w0 = g_wgt[2 * t], w1 = g_wgt[2 * t + 1];
    int sh = g_sharedBase + t;
    float4 c0 = *((const float4*)(g_c2 + (size_t)s0 * D_MODEL) + d4);
    float4 c1 = *((const float4*)(g_c2 + (size_t)s1 * D_MODEL) + d4);
    float4 cs = *((const float4*)(g_c2 + (size_t)sh * D_MODEL) + d4);
    float4 r;
    r.x = fmaf(w0, c0.x, fmaf(w1, c1.x, cs.x));
    r.y = fmaf(w0, c0.y, fmaf(w1, c1.y, cs.y));
    r.z = fmaf(w0, c0.z, fmaf(w1, c1.z, cs.z));
    r.w = fmaf(w0, c0.w, fmaf(w1, c1.w, cs.w));
    *((float4*)(out + (size_t)t * D_MODEL) + d4) = r;
}

// ---------------- launch ----------------
extern "C" void kernel_launch(void* const* d_in, const int* in_sizes, int n_in,
                              void* d_out, int out_size) {
    const float* x   = (const float*)d_in[0];
    const float* gw  = (const float*)d_in[1];
    const float* w1  = (const float*)d_in[2];
    const float* b1  = (const float*)d_in[3];
    const float* w2  = (const float*)d_in[4];
    const float* b2  = (const float*)d_in[5];
    const float* w3  = (const float*)d_in[6];
    const float* b3  = (const float*)d_in[7];
    const float* sw1 = (const float*)d_in[8];
    const float* sb1 = (const float*)d_in[9];
    const float* sw2 = (const float*)d_in[10];
    const float* sb2 = (const float*)d_in[11];
    const float* sw3 = (const float*)d_in[12];
    const float* sb3 = (const float*)d_in[13];
    float* out = (float*)d_out;

    gate_kernel<<<T_TOK / 4, 128>>>(x, gw);
    route_build<<<1, 1024>>>();
    dim3 grid1(INTER / 64, MAX_TILES);
    gemm_h<<<grid1, 256>>>(x, w1, b1, w3, b3, sw1, sb1, sw3, sb3);
    dim3 grid2(D_MODEL / 64, MAX_TILES);
    gemm_c2<<<grid2, 256>>>(w2, b2, sw2, sb2);
    combine_kernel<<<T_TOK, 256>>>(out);
}

// round 9
// speedup vs baseline: 1.7611x; 1.7611x over previous
#include <cuda_runtime.h>
#include <cuda_bf16.h>
#include <stdint.h>

#define D_MODEL 1024
#define INTER   1024
#define N_EXP   8
#define T_TOK   8192
#define MAX_TILES 208
#define MAX_ROWS  (MAX_TILES * 128)   // 26624

// ---------------- scratch (device globals: allocation-free) ----------------
__device__ float g_c1[(size_t)MAX_ROWS * INTER];    // X@W1 (+b1), then swiglu in-place
__device__ float g_c3[(size_t)MAX_ROWS * INTER];    // X@W3 (+b3)
__device__ float g_c2[(size_t)MAX_ROWS * D_MODEL];  // H@W2 (+b2)
__device__ int   g_srcTok[MAX_ROWS];
__device__ int   g_eid [T_TOK * 2];
__device__ float g_wgt [T_TOK * 2];
__device__ int   g_slot[T_TOK * 2];
__device__ int   g_tileExpert[MAX_TILES];
__device__ int   g_nTiles;
__device__ int   g_sharedBase;

// ---------------- warp-MMA helpers (baseline PTX, valid on sm_103 non-'a') ----
__device__ __forceinline__ uint32_t smem_u32(const void* p) {
    uint32_t a;
    asm("{ .reg .u64 t; cvta.to.shared.u64 t, %1; cvt.u32.u64 %0, t; }" : "=r"(a) : "l"(p));
    return a;
}
__device__ __forceinline__ void ldsm4(uint32_t* r, uint32_t a) {
    asm volatile("ldmatrix.sync.aligned.m8n8.x4.shared.b16 {%0,%1,%2,%3}, [%4];"
                 : "=r"(r[0]), "=r"(r[1]), "=r"(r[2]), "=r"(r[3]) : "r"(a));
}
__device__ __forceinline__ void ldsm4t(uint32_t* r, uint32_t a) {
    asm volatile("ldmatrix.sync.aligned.m8n8.x4.trans.shared.b16 {%0,%1,%2,%3}, [%4];"
                 : "=r"(r[0]), "=r"(r[1]), "=r"(r[2]), "=r"(r[3]) : "r"(a));
}
__device__ __forceinline__ void mma16816(float* d, const uint32_t* a, const uint32_t* b) {
    asm volatile("mma.sync.aligned.m16n8k16.row.col.f32.bf16.bf16.f32 "
                 "{%0,%1,%2,%3}, {%4,%5,%6,%7}, {%8,%9}, {%0,%1,%2,%3};"
                 : "+f"(d[0]), "+f"(d[1]), "+f"(d[2]), "+f"(d[3])
                 : "r"(a[0]), "r"(a[1]), "r"(a[2]), "r"(a[3]), "r"(b[0]), "r"(b[1]));
}

// split fp32x4 -> bf16 hi (4x2B) + bf16 lo, store 8B each
__device__ __forceinline__ void stHiLo(__nv_bfloat16* hp, __nv_bfloat16* lp, float4 v) {
    __nv_bfloat16 h0 = __float2bfloat16(v.x), h1 = __float2bfloat16(v.y),
                  h2 = __float2bfloat16(v.z), h3 = __float2bfloat16(v.w);
    float l0 = v.x - __bfloat162float(h0), l1 = v.y - __bfloat162float(h1),
          l2 = v.z - __bfloat162float(h2), l3 = v.w - __bfloat162float(h3);
    uint16_t u0 = *(uint16_t*)&h0, u1 = *(uint16_t*)&h1,
             u2 = *(uint16_t*)&h2, u3 = *(uint16_t*)&h3;
    uint2 hv = make_uint2((uint32_t)u0 | ((uint32_t)u1 << 16),
                          (uint32_t)u2 | ((uint32_t)u3 << 16));
    __nv_bfloat162 p0 = __floats2bfloat162_rn(l0, l1), p1 = __floats2bfloat162_rn(l2, l3);
    uint2 lv = make_uint2(*(uint32_t*)&p0, *(uint32_t*)&p1);
    *(uint2*)hp = hv;
    *(uint2*)lp = lv;
}

// ---------------- 1) gate: logits -> softmax -> top-2 (proven R7) ----------------
__global__ void gate_kernel(const float* __restrict__ x, const float* __restrict__ gw) {
    int warp = threadIdx.x >> 5, lane = threadIdx.x & 31;
    int t = blockIdx.x * 4 + warp;
    const float* xr = x + (size_t)t * D_MODEL;
    float xa[32];
#pragma unroll
    for (int i = 0; i < 32; i++) xa[i] = xr[lane + i * 32];
    float p[8];
#pragma unroll
    for (int e = 0; e < 8; e++) {
        const float* w = gw + e * D_MODEL;
        float s = 0.f;
#pragma unroll
        for (int i = 0; i < 32; i++) s += xa[i] * w[lane + i * 32];
#pragma unroll
        for (int off = 16; off > 0; off >>= 1) s += __shfl_xor_sync(0xffffffffu, s, off);
        p[e] = s;
    }
    float m = p[0];
#pragma unroll
    for (int e = 1; e < 8; e++) m = fmaxf(m, p[e]);
    float den = 0.f;
#pragma unroll
    for (int e = 0; e < 8; e++) { p[e] = __expf(p[e] - m); den += p[e]; }
    float inv = 1.f / den;
#pragma unroll
    for (int e = 0; e < 8; e++) p[e] *= inv;
    int i0 = 0;
#pragma unroll
    for (int e = 1; e < 8; e++) if (p[e] > p[i0]) i0 = e;
    int i1 = -1; float v1 = -1.f;
#pragma unroll
    for (int e = 0; e < 8; e++) if (e != i0 && p[e] > v1) { v1 = p[e]; i1 = e; }
    if (lane == 0) {
        g_eid[2 * t]     = i0; g_wgt[2 * t]     = p[i0];
        g_eid[2 * t + 1] = i1; g_wgt[2 * t + 1] = v1;
    }
}

// ---------------- 2) deterministic counting sort into 128-row tiles (proven R7) ----
__global__ void route_build() {
    __shared__ int warpsum[32][8];
    __shared__ int sExpBase[9];
    __shared__ int sExpCnt[8];
    int tid = threadIdx.x, lane = tid & 31, wid = tid >> 5;

    int lc[8];
#pragma unroll
    for (int e = 0; e < 8; e++) lc[e] = 0;
    int base = tid * 16;
    int eids[16];
#pragma unroll
    for (int j = 0; j < 16; j++) { int e = g_eid[base + j]; eids[j] = e; lc[e]++; }

    int incl[8];
#pragma unroll
    for (int e = 0; e < 8; e++) {
        int v = lc[e];
#pragma unroll
        for (int o = 1; o < 32; o <<= 1) {
            int n = __shfl_up_sync(0xffffffffu, v, o);
            if (lane >= o) v += n;
        }
        incl[e] = v;
        if (lane == 31) warpsum[wid][e] = v;
    }
    __syncthreads();
    if (tid < 256) {
        int e = tid >> 5, l = tid & 31;
        int v = warpsum[l][e];
#pragma unroll
        for (int o = 1; o < 32; o <<= 1) {
            int n = __shfl_up_sync(0xffffffffu, v, o);
            if (l >= o) v += n;
        }
        warpsum[l][e] = v;
    }
    __syncthreads();
    if (tid == 0) {
        int off = 0, nt = 0;
        for (int e = 0; e < 8; e++) {
            int c = warpsum[31][e];
            sExpBase[e] = off; sExpCnt[e] = c;
            int tiles = (c + 127) >> 7;
            for (int j = 0; j < tiles; j++) g_tileExpert[nt++] = e;
            off += tiles << 7;
        }
        sExpBase[8] = off;
        for (int j = 0; j < 64; j++) g_tileExpert[nt++] = 8;  // shared: 64 tiles
        g_nTiles = nt;
        g_sharedBase = off;
    }
    __syncthreads();

    int run[8];
#pragma unroll
    for (int e = 0; e < 8; e++) {
        int pw = (wid == 0) ? 0 : warpsum[wid - 1][e];
        run[e] = sExpBase[e] + pw + (incl[e] - lc[e]);
    }
#pragma unroll
    for (int j = 0; j < 16; j++) {
        int e = eids[j];
        int pos = run[e]++;
        g_srcTok[pos] = (base + j) >> 1;
        g_slot[base + j] = pos;
    }
    for (int e = 0; e < 8; e++) {
        int s = sExpBase[e] + sExpCnt[e], en = sExpBase[e + 1];
        for (int p = s + tid; p < en; p += 1024) g_srcTok[p] = -1;
    }
    int sb = sExpBase[8];
    for (int t = tid; t < T_TOK; t += 1024) g_srcTok[sb + t] = t;
}

// ---------------- 3) generic grouped GEMM: C = A(sel) @ W_e + bias_e ----------------
// bf16-split 3-product, block tile 128x64xKc32, 8 warps (warp tile 32x32)
#define PA 40   // A smem pitch (bf16 elems): 80B, conflict-free ldmatrix
#define PB 72   // B smem pitch: 144B, conflict-free ldmatrix.trans

__global__ __launch_bounds__(256, 2) void gemm_bf16s(
    const float* __restrict__ Asrc, int gather,
    const float* __restrict__ W, const float* __restrict__ sW,
    const float* __restrict__ bias, const float* __restrict__ sbias,
    float* __restrict__ C)
{
    int tileId = blockIdx.y;
    if (tileId >= g_nTiles) return;
    __shared__ __nv_bfloat16 Ah[128 * PA], Al[128 * PA];
    __shared__ __nv_bfloat16 Bh[32 * PB],  Bl[32 * PB];

    int tid = threadIdx.x, lane = tid & 31, warp = tid >> 5;
    int e = g_tileExpert[tileId];
    int rowBase = tileId << 7;
    int n0 = blockIdx.x << 6;
    const float* B0 = (e < N_EXP) ? (W + (size_t)e * 1024 * 1024) : sW;
    const float* bi = (e < N_EXP) ? (bias + e * 1024) : sbias;

    // loader mapping
    int arow = tid >> 1, ahalf = (tid & 1) * 16;        // A: 2 thr/row, 4 float4 each
    const float* aptr;
    bool aval;
    if (gather) {
        int t = g_srcTok[rowBase + arow];
        aval = (t >= 0);
        aptr = Asrc + (size_t)max(t, 0) * 1024 + ahalf;
    } else {
        aval = true;
        aptr = Asrc + (size_t)(rowBase + arow) * 1024 + ahalf;
    }
    int bkr = tid >> 3, bns = (tid & 7) * 8;            // B: 32 k-rows x 64 n
    const float* bptr = B0 + (size_t)bkr * 1024 + n0 + bns;

    float acc[2][4][4];
#pragma unroll
    for (int m = 0; m < 2; m++)
#pragma unroll
        for (int n = 0; n < 4; n++)
#pragma unroll
            for (int j = 0; j < 4; j++) acc[m][n][j] = 0.f;

    float4 ar[4], br[2];
#pragma unroll
    for (int q = 0; q < 4; q++)
        ar[q] = aval ? *(const float4*)(aptr + q * 4) : make_float4(0.f, 0.f, 0.f, 0.f);
    br[0] = *(const float4*)bptr;
    br[1] = *(const float4*)(bptr + 4);

    // warp layout: 4 (m) x 2 (n)
    int warpM = (warp >> 1) * 32, warpN = (warp & 1) * 32;
    uint32_t AhB = smem_u32(Ah), AlB = smem_u32(Al);
    uint32_t BhB = smem_u32(Bh), BlB = smem_u32(Bl);
    int lr = lane & 15, lcol = (lane >> 4) * 8;

    for (int c = 0; c < 32; c++) {
        __syncthreads();
        // store staged chunk to smem (fp32 -> bf16 hi/lo)
#pragma unroll
        for (int q = 0; q < 4; q++) {
            int o = arow * PA + ahalf + q * 4;
            stHiLo(&Ah[o], &Al[o], ar[q]);
        }
        {
            int o = bkr * PB + bns;
            stHiLo(&Bh[o], &Bl[o], br[0]);
            stHiLo(&Bh[o + 4], &Bl[o + 4], br[1]);
        }
        __syncthreads();
        if (c < 31) {   // prefetch next chunk (hidden under MMA)
            const float* ap = aptr + (c + 1) * 32;
#pragma unroll
            for (int q = 0; q < 4; q++)
                ar[q] = aval ? *(const float4*)(ap + q * 4) : make_float4(0.f, 0.f, 0.f, 0.f);
            const float* bp = bptr + (size_t)(c + 1) * 32 * 1024;
            br[0] = *(const float4*)bp;
            br[1] = *(const float4*)(bp + 4);
        }
#pragma unroll
        for (int ks = 0; ks < 2; ks++) {
            uint32_t ah[2][4], al[2][4];
#pragma unroll
            for (int m = 0; m < 2; m++) {
                uint32_t off = (uint32_t)((warpM + m * 16 + lr) * PA + ks * 16 + lcol) * 2;
                ldsm4(ah[m], AhB + off);
                ldsm4(al[m], AlB + off);
            }
            uint32_t bh[8], bl[8];
#pragma unroll
            for (int p = 0; p < 2; p++) {
                uint32_t off = (uint32_t)((ks * 16 + lr) * PB + warpN + p * 16 + lcol) * 2;
                ldsm4t(bh + 4 * p, BhB + off);
                ldsm4t(bl + 4 * p, BlB + off);
            }
#pragma unroll
            for (int m = 0; m < 2; m++)
#pragma unroll
                for (int n = 0; n < 4; n++) {
                    mma16816(acc[m][n], ah[m], bh + 2 * n);
                    mma16816(acc[m][n], ah[m], bl + 2 * n);
                    mma16816(acc[m][n], al[m], bh + 2 * n);
                }
        }
    }

    // epilogue: + bias, fp32 stores
    int g = lane >> 2, cc = (lane & 3) * 2;
#pragma unroll
    for (int m = 0; m < 2; m++) {
        int r0 = rowBase + warpM + m * 16 + g;
        float* C0 = C + (size_t)r0 * 1024;
        float* C1 = C0 + 8 * 1024;
#pragma unroll
        for (int n = 0; n < 4; n++) {
            int col = n0 + warpN + n * 8 + cc;
            float b0 = bi[col], b1 = bi[col + 1];
            *(float2*)&C0[col] = make_float2(acc[m][n][0] + b0, acc[m][n][1] + b1);
            *(float2*)&C1[col] = make_float2(acc[m][n][2] + b0, acc[m][n][3] + b1);
        }
    }
}

// ---------------- 4) SwiGLU elementwise: c1 = silu(c1) * c3 ----------------
__global__ void swiglu_kernel() {
    if ((int)blockIdx.y >= g_nTiles) return;
    size_t idx = (size_t)blockIdx.y * 131072 + blockIdx.x * 1024 + threadIdx.x * 4;
    float4 a = *(float4*)&g_c1[idx];
    float4 u = *(float4*)&g_c3[idx];
    float4 r;
    r.x = a.x / (1.f + __expf(-a.x)) * u.x;
    r.y = a.y / (1.f + __expf(-a.y)) * u.y;
    r.z = a.z / (1.f + __expf(-a.z)) * u.z;
    r.w = a.w / (1.f + __expf(-a.w)) * u.w;
    *(float4*)&g_c1[idx] = r;
}

// ---------------- 5) combine: out[t] = w0*C2[s0] + w1*C2[s1] + C2[shared_t] -------
__global__ void combine_kernel(float* __restrict__ out) {
    int t = blockIdx.x;
    int d4 = threadIdx.x;
    int s0 = g_slot[2 * t], s1 = g_slot[2 * t + 1];
    float w0 = g_wgt[2 * t], w1 = g_wgt[2 * t + 1];
    int sh = g_sharedBase + t;
    float4 c0 = *((const float4*)(g_c2 + (size_t)s0 * D_MODEL) + d4);
    float4 c1 = *((const float4*)(g_c2 + (size_t)s1 * D_MODEL) + d4);
    float4 cs = *((const float4*)(g_c2 + (size_t)sh * D_MODEL) + d4);
    float4 r;
    r.x = fmaf(w0, c0.x, fmaf(w1, c1.x, cs.x));
    r.y = fmaf(w0, c0.y, fmaf(w1, c1.y, cs.y));
    r.z = fmaf(w0, c0.z, fmaf(w1, c1.z, cs.z));
    r.w = fmaf(w0, c0.w, fmaf(w1, c1.w, cs.w));
    *((float4*)(out + (size_t)t * D_MODEL) + d4) = r;
}

// ---------------- launch ----------------
extern "C" void kernel_launch(void* const* d_in, const int* in_sizes, int n_in,
                              void* d_out, int out_size) {
    const float* x   = (const float*)d_in[0];
    const float* gw  = (const float*)d_in[1];
    const float* w1  = (const float*)d_in[2];
    const float* b1  = (const float*)d_in[3];
    const float* w2  = (const float*)d_in[4];
    const float* b2  = (const float*)d_in[5];
    const float* w3  = (const float*)d_in[6];
    const float* b3  = (const float*)d_in[7];
    const float* sw1 = (const float*)d_in[8];
    const float* sb1 = (const float*)d_in[9];
    const float* sw2 = (const float*)d_in[10];
    const float* sb2 = (const float*)d_in[11];
    const float* sw3 = (const float*)d_in[12];
    const float* sb3 = (const float*)d_in[13];
    float* out = (float*)d_out;

    float* c1; cudaGetSymbolAddress((void**)&c1, g_c1);
    float* c3; cudaGetSymbolAddress((void**)&c3, g_c3);
    float* c2; cudaGetSymbolAddress((void**)&c2, g_c2);

    gate_kernel<<<T_TOK / 4, 128>>>(x, gw);
    route_build<<<1, 1024>>>();
    dim3 grid(16, MAX_TILES);
    gemm_bf16s<<<grid, 256>>>(x, 1, w1, sw1, b1, sb1, c1);
    gemm_bf16s<<<grid, 256>>>(x, 1, w3, sw3, b3, sb3, c3);
    swiglu_kernel<<<dim3(128, MAX_TILES), 256>>>();
    gemm_bf16s<<<grid, 256>>>(c1, 0, w2, sw2, b2, sb2, c2);
    combine_kernel<<<T_TOK, 256>>>(out);
}

// round 13
// speedup vs baseline: 1.9029x; 1.0805x over previous
#include <cuda_runtime.h>
#include <cuda_bf16.h>
#include <stdint.h>

#define D_MODEL 1024
#define INTER   1024
#define N_EXP   8
#define T_TOK   8192
#define MAX_TILES 208
#define MAX_ROWS  (MAX_TILES * 128)   // 26624

// ---------------- scratch (device globals: allocation-free) ----------------
__device__ __nv_bfloat16 g_xh[(size_t)T_TOK * 1024], g_xl[(size_t)T_TOK * 1024];
__device__ __nv_bfloat16 g_wh[27ull * 1024 * 1024],  g_wl[27ull * 1024 * 1024];
__device__ __nv_bfloat16 g_hh[(size_t)MAX_ROWS * 1024], g_hl[(size_t)MAX_ROWS * 1024];
__device__ float g_c1[(size_t)MAX_ROWS * INTER];
__device__ float g_c3[(size_t)MAX_ROWS * INTER];
__device__ float g_c2[(size_t)MAX_ROWS * D_MODEL];
__device__ int   g_srcTok[MAX_ROWS];
__device__ int   g_eid [T_TOK * 2];
__device__ float g_wgt [T_TOK * 2];
__device__ int   g_slot[T_TOK * 2];
__device__ int   g_tileExpert[MAX_TILES];
__device__ int   g_nTiles;
__device__ int   g_sharedBase;

// ---------------- helpers ----------------
__device__ __forceinline__ uint32_t smem_u32(const void* p) {
    uint32_t a;
    asm("{ .reg .u64 t; cvta.to.shared.u64 t, %1; cvt.u32.u64 %0, t; }" : "=r"(a) : "l"(p));
    return a;
}
__device__ __forceinline__ void ldsm4(uint32_t* r, uint32_t a) {
    asm volatile("ldmatrix.sync.aligned.m8n8.x4.shared.b16 {%0,%1,%2,%3}, [%4];"
                 : "=r"(r[0]), "=r"(r[1]), "=r"(r[2]), "=r"(r[3]) : "r"(a));
}
__device__ __forceinline__ void ldsm4t(uint32_t* r, uint32_t a) {
    asm volatile("ldmatrix.sync.aligned.m8n8.x4.trans.shared.b16 {%0,%1,%2,%3}, [%4];"
                 : "=r"(r[0]), "=r"(r[1]), "=r"(r[2]), "=r"(r[3]) : "r"(a));
}
__device__ __forceinline__ void mma16816(float* d, const uint32_t* a, const uint32_t* b) {
    asm volatile("mma.sync.aligned.m16n8k16.row.col.f32.bf16.bf16.f32 "
                 "{%0,%1,%2,%3}, {%4,%5,%6,%7}, {%8,%9}, {%0,%1,%2,%3};"
                 : "+f"(d[0]), "+f"(d[1]), "+f"(d[2]), "+f"(d[3])
                 : "r"(a[0]), "r"(a[1]), "r"(a[2]), "r"(a[3]), "r"(b[0]), "r"(b[1]));
}
__device__ __forceinline__ void cpa16(uint32_t dst, const void* src, uint32_t sz) {
    asm volatile("cp.async.cg.shared.global [%0], [%1], 16, %2;"
                 :: "r"(dst), "l"(src), "r"(sz) : "memory");
}
#define CP_COMMIT() asm volatile("cp.async.commit_group;" ::: "memory")
#define CP_WAIT0()  asm volatile("cp.async.wait_group 0;" ::: "memory")

// split fp32x4 -> bf16 hi (8B) + bf16 lo (8B)
__device__ __forceinline__ void stHiLo(__nv_bfloat16* hp, __nv_bfloat16* lp, float4 v) {
    __nv_bfloat16 h0 = __float2bfloat16(v.x), h1 = __float2bfloat16(v.y),
                  h2 = __float2bfloat16(v.z), h3 = __float2bfloat16(v.w);
    float l0 = v.x - __bfloat162float(h0), l1 = v.y - __bfloat162float(h1),
          l2 = v.z - __bfloat162float(h2), l3 = v.w - __bfloat162float(h3);
    uint16_t u0 = *(uint16_t*)&h0, u1 = *(uint16_t*)&h1,
             u2 = *(uint16_t*)&h2, u3 = *(uint16_t*)&h3;
    uint2 hv = make_uint2((uint32_t)u0 | ((uint32_t)u1 << 16),
                          (uint32_t)u2 | ((uint32_t)u3 << 16));
    __nv_bfloat162 p0 = __floats2bfloat162_rn(l0, l1), p1 = __floats2bfloat162_rn(l2, l3);
    uint2 lv = make_uint2(*(uint32_t*)&p0, *(uint32_t*)&p1);
    *(uint2*)hp = hv;
    *(uint2*)lp = lv;
}

// ---------------- 0a) convert weights fp32 -> bf16 hi/lo planes ----------------
// z: 0..8 = w1/sw1, 9..17 = w3/sw3, 18..26 = w2/sw2 (shared at local index 8)
__global__ void prep_w(const float* __restrict__ w1, const float* __restrict__ w3,
                       const float* __restrict__ w2, const float* __restrict__ sw1,
                       const float* __restrict__ sw3, const float* __restrict__ sw2) {
    int z = blockIdx.y;
    const float* src;
    if (z < 9)       src = (z < 8) ? w1 + (size_t)z * 1048576 : sw1;
    else if (z < 18) { int e = z - 9;  src = (e < 8) ? w3 + (size_t)e * 1048576 : sw3; }
    else             { int e = z - 18; src = (e < 8) ? w2 + (size_t)e * 1048576 : sw2; }
    size_t off = (size_t)blockIdx.x * 1024 + threadIdx.x * 4;
    float4 v = *(const float4*)(src + off);
    size_t o = (size_t)z * 1048576 + off;
    stHiLo(&g_wh[o], &g_wl[o], v);
}

// ---------------- 0b) convert x fp32 -> bf16 hi/lo ----------------
__global__ void prep_x(const float* __restrict__ x) {
    size_t off = (size_t)blockIdx.x * 1024 + threadIdx.x * 4;
    float4 v = *(const float4*)(x + off);
    stHiLo(&g_xh[off], &g_xl[off], v);
}

// ---------------- 1) gate: logits -> softmax -> top-2 (proven) ----------------
__global__ void gate_kernel(const float* __restrict__ x, const float* __restrict__ gw) {
    int warp = threadIdx.x >> 5, lane = threadIdx.x & 31;
    int t = blockIdx.x * 4 + warp;
    const float* xr = x + (size_t)t * D_MODEL;
    float xa[32];
#pragma unroll
    for (int i = 0; i < 32; i++) xa[i] = xr[lane + i * 32];
    float p[8];
#pragma unroll
    for (int e = 0; e < 8; e++) {
        const float* w = gw + e * D_MODEL;
        float s = 0.f;
#pragma unroll
        for (int i = 0; i < 32; i++) s += xa[i] * w[lane + i * 32];
#pragma unroll
        for (int off = 16; off > 0; off >>= 1) s += __shfl_xor_sync(0xffffffffu, s, off);
        p[e] = s;
    }
    float m = p[0];
#pragma unroll
    for (int e = 1; e < 8; e++) m = fmaxf(m, p[e]);
    float den = 0.f;
#pragma unroll
    for (int e = 0; e < 8; e++) { p[e] = __expf(p[e] - m); den += p[e]; }
    float inv = 1.f / den;
#pragma unroll
    for (int e = 0; e < 8; e++) p[e] *= inv;
    int i0 = 0;
#pragma unroll
    for (int e = 1; e < 8; e++) if (p[e] > p[i0]) i0 = e;
    int i1 = -1; float v1 = -1.f;
#pragma unroll
    for (int e = 0; e < 8; e++) if (e != i0 && p[e] > v1) { v1 = p[e]; i1 = e; }
    if (lane == 0) {
        g_eid[2 * t]     = i0; g_wgt[2 * t]     = p[i0];
        g_eid[2 * t + 1] = i1; g_wgt[2 * t + 1] = v1;
    }
}

// ---------------- 2) deterministic counting sort into 128-row tiles (proven) -----
__global__ void route_build() {
    __shared__ int warpsum[32][8];
    __shared__ int sExpBase[9];
    __shared__ int sExpCnt[8];
    int tid = threadIdx.x, lane = tid & 31, wid = tid >> 5;

    int lc[8];
#pragma unroll
    for (int e = 0; e < 8; e++) lc[e] = 0;
    int base = tid * 16;
    int eids[16];
#pragma unroll
    for (int j = 0; j < 16; j++) { int e = g_eid[base + j]; eids[j] = e; lc[e]++; }

    int incl[8];
#pragma unroll
    for (int e = 0; e < 8; e++) {
        int v = lc[e];
#pragma unroll
        for (int o = 1; o < 32; o <<= 1) {
            int n = __shfl_up_sync(0xffffffffu, v, o);
            if (lane >= o) v += n;
        }
        incl[e] = v;
        if (lane == 31) warpsum[wid][e] = v;
    }
    __syncthreads();
    if (tid < 256) {
        int e = tid >> 5, l = tid & 31;
        int v = warpsum[l][e];
#pragma unroll
        for (int o = 1; o < 32; o <<= 1) {
            int n = __shfl_up_sync(0xffffffffu, v, o);
            if (l >= o) v += n;
        }
        warpsum[l][e] = v;
    }
    __syncthreads();
    if (tid == 0) {
        int off = 0, nt = 0;
        for (int e = 0; e < 8; e++) {
            int c = warpsum[31][e];
            sExpBase[e] = off; sExpCnt[e] = c;
            int tiles = (c + 127) >> 7;
            for (int j = 0; j < tiles; j++) g_tileExpert[nt++] = e;
            off += tiles << 7;
        }
        sExpBase[8] = off;
        for (int j = 0; j < 64; j++) g_tileExpert[nt++] = 8;
        g_nTiles = nt;
        g_sharedBase = off;
    }
    __syncthreads();

    int run[8];
#pragma unroll
    for (int e = 0; e < 8; e++) {
        int pw = (wid == 0) ? 0 : warpsum[wid - 1][e];
        run[e] = sExpBase[e] + pw + (incl[e] - lc[e]);
    }
#pragma unroll
    for (int j = 0; j < 16; j++) {
        int e = eids[j];
        int pos = run[e]++;
        g_srcTok[pos] = (base + j) >> 1;
        g_slot[base + j] = pos;
    }
    for (int e = 0; e < 8; e++) {
        int s = sExpBase[e] + sExpCnt[e], en = sExpBase[e + 1];
        for (int p = s + tid; p < en; p += 1024) g_srcTok[p] = -1;
    }
    int sb = sExpBase[8];
    for (int t = tid; t < T_TOK; t += 1024) g_srcTok[sb + t] = t;
}

// ---------------- 3) grouped GEMM: C = A @ W_z + bias, bf16 hi/lo 3-product ------
// block 128x128xKc32, 4 warps (64x64 each), cp.async double-buffered smem
#define PAE 40    // A smem pitch (elems): 80B, ldmatrix conflict-free
#define PBE 136   // B smem pitch (elems): 272B, ldmatrix.trans conflict-free
// dyn smem (bytes): AH[2]@0 (10240 ea), AL[2]@20480, BH[2]@40960 (8704 ea), BL[2]@58368
#define SMEM_GEMM 75776

__global__ __launch_bounds__(128, 2) void gemm_hilo(
    const __nv_bfloat16* __restrict__ Agh, const __nv_bfloat16* __restrict__ Agl,
    int gather, int zbase,
    const float* __restrict__ bias, const float* __restrict__ sbias,
    float* __restrict__ C)
{
    int tileId = blockIdx.y;
    if (tileId >= g_nTiles) return;
    extern __shared__ char sm[];
    uint32_t smb = smem_u32(sm);
    int tid = threadIdx.x, lane = tid & 31, warp = tid >> 5;
    int e = g_tileExpert[tileId];
    int rowBase = tileId << 7;
    int n0 = blockIdx.x << 7;

    const __nv_bfloat16* Wh = g_wh + (size_t)(zbase + e) * 1048576;
    const __nv_bfloat16* Wl = g_wl + (size_t)(zbase + e) * 1048576;
    const float* bi = (e < N_EXP) ? (bias + e * 1024) : sbias;

    // A loader: one row per thread
    int tokA; uint32_t aSz;
    if (gather) { tokA = g_srcTok[rowBase + tid]; aSz = (tokA >= 0) ? 16u : 0u; }
    else        { tokA = rowBase + tid;           aSz = 16u; }
    const __nv_bfloat16* aSrcH = Agh + (size_t)max(tokA, 0) * 1024;
    const __nv_bfloat16* aSrcL = Agl + (size_t)max(tokA, 0) * 1024;
    uint32_t aDstH = smb + tid * 80;
    uint32_t aDstL = smb + 20480 + tid * 80;

    // B loader: 4 threads per k-row, 64B segments
    int brow = tid >> 2, bcs = (tid & 3) * 32;
    const __nv_bfloat16* bSrcH = Wh + (size_t)brow * 1024 + n0 + bcs;
    const __nv_bfloat16* bSrcL = Wl + (size_t)brow * 1024 + n0 + bcs;
    uint32_t bDstH = smb + 40960 + brow * 272 + bcs * 2;
    uint32_t bDstL = smb + 58368 + brow * 272 + bcs * 2;

    auto issue = [&](int c) {
        int s = c & 1;
        const __nv_bfloat16* ah = aSrcH + c * 32;
        const __nv_bfloat16* al = aSrcL + c * 32;
        uint32_t da = s * 10240;
#pragma unroll
        for (int q = 0; q < 4; q++) {
            cpa16(aDstH + da + q * 16, ah + q * 8, aSz);
            cpa16(aDstL + da + q * 16, al + q * 8, aSz);
        }
        const __nv_bfloat16* bh = bSrcH + (size_t)c * 32 * 1024;
        const __nv_bfloat16* bl = bSrcL + (size_t)c * 32 * 1024;
        uint32_t db = s * 8704;
#pragma unroll
        for (int q = 0; q < 4; q++) {
            cpa16(bDstH + db + q * 16, bh + q * 8, 16u);
            cpa16(bDstL + db + q * 16, bl + q * 8, 16u);
        }
        CP_COMMIT();
    };

    float acc[4][8][4];
#pragma unroll
    for (int m = 0; m < 4; m++)
#pragma unroll
        for (int n = 0; n < 8; n++)
#pragma unroll
            for (int j = 0; j < 4; j++) acc[m][n][j] = 0.f;

    int warpM = (warp >> 1) * 64, warpN = (warp & 1) * 64;
    int lr = lane & 15, lcol = (lane >> 4) * 8;

    issue(0);
    for (int c = 0; c < 32; c++) {
        CP_WAIT0();
        __syncthreads();
        if (c + 1 < 32) issue(c + 1);   // overlaps with MMA below
        int s = c & 1;
        uint32_t AHs = smb + s * 10240, ALs = smb + 20480 + s * 10240;
        uint32_t BHs = smb + 40960 + s * 8704, BLs = smb + 58368 + s * 8704;
#pragma unroll
        for (int ks = 0; ks < 2; ks++) {
            uint32_t ah[4][4], al[4][4];
#pragma unroll
            for (int m = 0; m < 4; m++) {
                uint32_t o = (uint32_t)((warpM + m * 16 + lr) * PAE + ks * 16 + lcol) * 2;
                ldsm4(ah[m], AHs + o);
                ldsm4(al[m], ALs + o);
            }
#pragma unroll
            for (int np = 0; np < 4; np++) {
                uint32_t bh[4], bl[4];
                uint32_t o = (uint32_t)((ks * 16 + lr) * PBE + warpN + np * 16 + lcol) * 2;
                ldsm4t(bh, BHs + o);
                ldsm4t(bl, BLs + o);
#pragma unroll
                for (int m = 0; m < 4; m++) {
                    mma16816(acc[m][2 * np],     ah[m], bh);
                    mma16816(acc[m][2 * np],     ah[m], bl);
                    mma16816(acc[m][2 * np],     al[m], bh);
                    mma16816(acc[m][2 * np + 1], ah[m], bh + 2);
                    mma16816(acc[m][2 * np + 1], ah[m], bl + 2);
                    mma16816(acc[m][2 * np + 1], al[m], bh + 2);
                }
            }
        }
    }

    // epilogue: + bias, fp32 stores
    int g = lane >> 2, cc = (lane & 3) * 2;
#pragma unroll
    for (int m = 0; m < 4; m++) {
        int r0 = rowBase + warpM + m * 16 + g;
        float* C0 = C + (size_t)r0 * 1024;
        float* C1 = C0 + 8 * 1024;
#pragma unroll
        for (int n = 0; n < 8; n++) {
            int col = n0 + warpN + n * 8 + cc;
            float b0 = bi[col], b1 = bi[col + 1];
            *(float2*)&C0[col] = make_float2(acc[m][n][0] + b0, acc[m][n][1] + b1);
            *(float2*)&C1[col] = make_float2(acc[m][n][2] + b0, acc[m][n][3] + b1);
        }
    }
}

// ---------------- 4) SwiGLU: h = silu(c1)*c3, write bf16 hi/lo ----------------
__global__ void swiglu_kernel() {
    if ((int)blockIdx.y >= g_nTiles) return;
    size_t idx = (size_t)blockIdx.y * 131072 + blockIdx.x * 1024 + threadIdx.x * 4;
    float4 a = *(float4*)&g_c1[idx];
    float4 u = *(float4*)&g_c3[idx];
    float4 h;
    h.x = a.x / (1.f + __expf(-a.x)) * u.x;
    h.y = a.y / (1.f + __expf(-a.y)) * u.y;
    h.z = a.z / (1.f + __expf(-a.z)) * u.z;
    h.w = a.w / (1.f + __expf(-a.w)) * u.w;
    stHiLo(&g_hh[idx], &g_hl[idx], h);
}

// ---------------- 5) combine: out[t] = w0*C2[s0] + w1*C2[s1] + C2[shared_t] -----
__global__ void combine_kernel(float* __restrict__ out) {
    int t = blockIdx.x;
    int d4 = threadIdx.x;
    int s0 = g_slot[2 * t], s1 = g_slot[2 * t + 1];
    float w0 = g_wgt[2 * t], w1 = g_wgt[2 * t + 1];
    int sh = g_sharedBase + t;
    float4 c0 = *((const float4*)(g_c2 + (size_t)s0 * D_MODEL) + d4);
    float4 c1 = *((const float4*)(g_c2 + (size_t)s1 * D_MODEL) + d4);
    float4 cs = *((const float4*)(g_c2 + (size_t)sh * D_MODEL) + d4);
    float4 r;
    r.x = fmaf(w0, c0.x, fmaf(w1, c1.x, cs.x));
    r.y = fmaf(w0, c0.y, fmaf(w1, c1.y, cs.y));
    r.z = fmaf(w0, c0.z, fmaf(w1, c1.z, cs.z));
    r.w = fmaf(w0, c0.w, fmaf(w1, c1.w, cs.w));
    *((float4*)(out + (size_t)t * D_MODEL) + d4) = r;
}

// ---------------- launch ----------------
extern "C" void kernel_launch(void* const* d_in, const int* in_sizes, int n_in,
                              void* d_out, int out_size) {
    const float* x   = (const float*)d_in[0];
    const float* gw  = (const float*)d_in[1];
    const float* w1  = (const float*)d_in[2];
    const float* b1  = (const float*)d_in[3];
    const float* w2  = (const float*)d_in[4];
    const float* b2  = (const float*)d_in[5];
    const float* w3  = (const float*)d_in[6];
    const float* b3  = (const float*)d_in[7];
    const float* sw1 = (const float*)d_in[8];
    const float* sb1 = (const float*)d_in[9];
    const float* sw2 = (const float*)d_in[10];
    const float* sb2 = (const float*)d_in[11];
    const float* sw3 = (const float*)d_in[12];
    const float* sb3 = (const float*)d_in[13];
    float* out = (float*)d_out;

    __nv_bfloat16 *xh, *xl, *hh, *hl;
    float *c1, *c3, *c2;
    cudaGetSymbolAddress((void**)&xh, g_xh);
    cudaGetSymbolAddress((void**)&xl, g_xl);
    cudaGetSymbolAddress((void**)&hh, g_hh);
    cudaGetSymbolAddress((void**)&hl, g_hl);
    cudaGetSymbolAddress((void**)&c1, g_c1);
    cudaGetSymbolAddress((void**)&c3, g_c3);
    cudaGetSymbolAddress((void**)&c2, g_c2);

    cudaFuncSetAttribute(gemm_hilo, cudaFuncAttributeMaxDynamicSharedMemorySize, SMEM_GEMM);

    prep_w<<<dim3(1024, 27), 256>>>(w1, w3, w2, sw1, sw3, sw2);
    prep_x<<<T_TOK, 256>>>(x);
    gate_kernel<<<T_TOK / 4, 128>>>(x, gw);
    route_build<<<1, 1024>>>();
    dim3 gg(8, MAX_TILES);
    gemm_hilo<<<gg, 128, SMEM_GEMM>>>(xh, xl, 1, 0,  b1, sb1, c1);
    gemm_hilo<<<gg, 128, SMEM_GEMM>>>(xh, xl, 1, 9,  b3, sb3, c3);
    swiglu_kernel<<<dim3(128, MAX_TILES), 256>>>();
    gemm_hilo<<<gg, 128, SMEM_GEMM>>>(hh, hl, 0, 18, b2, sb2, c2);
    combine_kernel<<<T_TOK, 256>>>(out);
}

// round 14
// speedup vs baseline: 1.9703x; 1.0354x over previous
#include <cuda_runtime.h>
#include <cuda_bf16.h>
#include <stdint.h>

#define D_MODEL 1024
#define INTER   1024
#define N_EXP   8
#define T_TOK   8192
#define MAX_TILES 208
#define MAX_ROWS  (MAX_TILES * 128)   // 26624

// ---------------- scratch (device globals: allocation-free) ----------------
__device__ __nv_bfloat16 g_xh[(size_t)T_TOK * 1024], g_xl[(size_t)T_TOK * 1024];
__device__ __nv_bfloat16 g_wh[27ull * 1024 * 1024],  g_wl[27ull * 1024 * 1024];
__device__ __nv_bfloat16 g_hh[(size_t)MAX_ROWS * 1024], g_hl[(size_t)MAX_ROWS * 1024];
__device__ float g_c2[(size_t)MAX_ROWS * D_MODEL];
__device__ int   g_srcTok[MAX_ROWS];
__device__ int   g_eid [T_TOK * 2];
__device__ float g_wgt [T_TOK * 2];
__device__ int   g_slot[T_TOK * 2];
__device__ int   g_tileExpert[MAX_TILES];
__device__ int   g_nTiles;
__device__ int   g_sharedBase;

// ---------------- helpers ----------------
__device__ __forceinline__ uint32_t smem_u32(const void* p) {
    uint32_t a;
    asm("{ .reg .u64 t; cvta.to.shared.u64 t, %1; cvt.u32.u64 %0, t; }" : "=r"(a) : "l"(p));
    return a;
}
__device__ __forceinline__ void ldsm4(uint32_t* r, uint32_t a) {
    asm volatile("ldmatrix.sync.aligned.m8n8.x4.shared.b16 {%0,%1,%2,%3}, [%4];"
                 : "=r"(r[0]), "=r"(r[1]), "=r"(r[2]), "=r"(r[3]) : "r"(a));
}
__device__ __forceinline__ void ldsm4t(uint32_t* r, uint32_t a) {
    asm volatile("ldmatrix.sync.aligned.m8n8.x4.trans.shared.b16 {%0,%1,%2,%3}, [%4];"
                 : "=r"(r[0]), "=r"(r[1]), "=r"(r[2]), "=r"(r[3]) : "r"(a));
}
__device__ __forceinline__ void mma16816(float* d, const uint32_t* a, const uint32_t* b) {
    asm volatile("mma.sync.aligned.m16n8k16.row.col.f32.bf16.bf16.f32 "
                 "{%0,%1,%2,%3}, {%4,%5,%6,%7}, {%8,%9}, {%0,%1,%2,%3};"
                 : "+f"(d[0]), "+f"(d[1]), "+f"(d[2]), "+f"(d[3])
                 : "r"(a[0]), "r"(a[1]), "r"(a[2]), "r"(a[3]), "r"(b[0]), "r"(b[1]));
}
__device__ __forceinline__ void cpa16(uint32_t dst, const void* src, uint32_t sz) {
    asm volatile("cp.async.cg.shared.global [%0], [%1], 16, %2;"
                 :: "r"(dst), "l"(src), "r"(sz) : "memory");
}
#define CP_COMMIT() asm volatile("cp.async.commit_group;" ::: "memory")
#define CP_WAIT0()  asm volatile("cp.async.wait_group 0;" ::: "memory")

// split fp32x4 -> bf16 hi (8B) + bf16 lo (8B)
__device__ __forceinline__ void stHiLo(__nv_bfloat16* hp, __nv_bfloat16* lp, float4 v) {
    __nv_bfloat16 h0 = __float2bfloat16(v.x), h1 = __float2bfloat16(v.y),
                  h2 = __float2bfloat16(v.z), h3 = __float2bfloat16(v.w);
    float l0 = v.x - __bfloat162float(h0), l1 = v.y - __bfloat162float(h1),
          l2 = v.z - __bfloat162float(h2), l3 = v.w - __bfloat162float(h3);
    uint16_t u0 = *(uint16_t*)&h0, u1 = *(uint16_t*)&h1,
             u2 = *(uint16_t*)&h2, u3 = *(uint16_t*)&h3;
    uint2 hv = make_uint2((uint32_t)u0 | ((uint32_t)u1 << 16),
                          (uint32_t)u2 | ((uint32_t)u3 << 16));
    __nv_bfloat162 p0 = __floats2bfloat162_rn(l0, l1), p1 = __floats2bfloat162_rn(l2, l3);
    uint2 lv = make_uint2(*(uint32_t*)&p0, *(uint32_t*)&p1);
    *(uint2*)hp = hv;
    *(uint2*)lp = lv;
}
// split pair -> bf16 hi/lo 2-elem stores
__device__ __forceinline__ void stHiLo2(__nv_bfloat16* hp, __nv_bfloat16* lp,
                                        float a, float b) {
    __nv_bfloat16 h0 = __float2bfloat16(a), h1 = __float2bfloat16(b);
    float l0 = a - __bfloat162float(h0), l1 = b - __bfloat162float(h1);
    uint16_t u0 = *(uint16_t*)&h0, u1 = *(uint16_t*)&h1;
    uint32_t hv = (uint32_t)u0 | ((uint32_t)u1 << 16);
    __nv_bfloat162 p = __floats2bfloat162_rn(l0, l1);
    *(uint32_t*)hp = hv;
    *(uint32_t*)lp = *(uint32_t*)&p;
}

// ---------------- 0a) weights fp32 -> bf16 hi/lo planes ----------------
__global__ void prep_w(const float* __restrict__ w1, const float* __restrict__ w3,
                       const float* __restrict__ w2, const float* __restrict__ sw1,
                       const float* __restrict__ sw3, const float* __restrict__ sw2) {
    int z = blockIdx.y;
    const float* src;
    if (z < 9)       src = (z < 8) ? w1 + (size_t)z * 1048576 : sw1;
    else if (z < 18) { int e = z - 9;  src = (e < 8) ? w3 + (size_t)e * 1048576 : sw3; }
    else             { int e = z - 18; src = (e < 8) ? w2 + (size_t)e * 1048576 : sw2; }
    size_t off = (size_t)blockIdx.x * 1024 + threadIdx.x * 4;
    float4 v = *(const float4*)(src + off);
    size_t o = (size_t)z * 1048576 + off;
    stHiLo(&g_wh[o], &g_wl[o], v);
}

// ---------------- 0b) x fp32 -> bf16 hi/lo ----------------
__global__ void prep_x(const float* __restrict__ x) {
    size_t off = (size_t)blockIdx.x * 1024 + threadIdx.x * 4;
    float4 v = *(const float4*)(x + off);
    stHiLo(&g_xh[off], &g_xl[off], v);
}

// ---------------- 1) gate (proven) ----------------
__global__ void gate_kernel(const float* __restrict__ x, const float* __restrict__ gw) {
    int warp = threadIdx.x >> 5, lane = threadIdx.x & 31;
    int t = blockIdx.x * 4 + warp;
    const float* xr = x + (size_t)t * D_MODEL;
    float xa[32];
#pragma unroll
    for (int i = 0; i < 32; i++) xa[i] = xr[lane + i * 32];
    float p[8];
#pragma unroll
    for (int e = 0; e < 8; e++) {
        const float* w = gw + e * D_MODEL;
        float s = 0.f;
#pragma unroll
        for (int i = 0; i < 32; i++) s += xa[i] * w[lane + i * 32];
#pragma unroll
        for (int off = 16; off > 0; off >>= 1) s += __shfl_xor_sync(0xffffffffu, s, off);
        p[e] = s;
    }
    float m = p[0];
#pragma unroll
    for (int e = 1; e < 8; e++) m = fmaxf(m, p[e]);
    float den = 0.f;
#pragma unroll
    for (int e = 0; e < 8; e++) { p[e] = __expf(p[e] - m); den += p[e]; }
    float inv = 1.f / den;
#pragma unroll
    for (int e = 0; e < 8; e++) p[e] *= inv;
    int i0 = 0;
#pragma unroll
    for (int e = 1; e < 8; e++) if (p[e] > p[i0]) i0 = e;
    int i1 = -1; float v1 = -1.f;
#pragma unroll
    for (int e = 0; e < 8; e++) if (e != i0 && p[e] > v1) { v1 = p[e]; i1 = e; }
    if (lane == 0) {
        g_eid[2 * t]     = i0; g_wgt[2 * t]     = p[i0];
        g_eid[2 * t + 1] = i1; g_wgt[2 * t + 1] = v1;
    }
}

// ---------------- 2) deterministic counting sort (proven) ----------------
__global__ void route_build() {
    __shared__ int warpsum[32][8];
    __shared__ int sExpBase[9];
    __shared__ int sExpCnt[8];
    int tid = threadIdx.x, lane = tid & 31, wid = tid >> 5;

    int lc[8];
#pragma unroll
    for (int e = 0; e < 8; e++) lc[e] = 0;
    int base = tid * 16;
    int eids[16];
#pragma unroll
    for (int j = 0; j < 16; j++) { int e = g_eid[base + j]; eids[j] = e; lc[e]++; }

    int incl[8];
#pragma unroll
    for (int e = 0; e < 8; e++) {
        int v = lc[e];
#pragma unroll
        for (int o = 1; o < 32; o <<= 1) {
            int n = __shfl_up_sync(0xffffffffu, v, o);
            if (lane >= o) v += n;
        }
        incl[e] = v;
        if (lane == 31) warpsum[wid][e] = v;
    }
    __syncthreads();
    if (tid < 256) {
        int e = tid >> 5, l = tid & 31;
        int v = warpsum[l][e];
#pragma unroll
        for (int o = 1; o < 32; o <<= 1) {
            int n = __shfl_up_sync(0xffffffffu, v, o);
            if (l >= o) v += n;
        }
        warpsum[l][e] = v;
    }
    __syncthreads();
    if (tid == 0) {
        int off = 0, nt = 0;
        for (int e = 0; e < 8; e++) {
            int c = warpsum[31][e];
            sExpBase[e] = off; sExpCnt[e] = c;
            int tiles = (c + 127) >> 7;
            for (int j = 0; j < tiles; j++) g_tileExpert[nt++] = e;
            off += tiles << 7;
        }
        sExpBase[8] = off;
        for (int j = 0; j < 64; j++) g_tileExpert[nt++] = 8;
        g_nTiles = nt;
        g_sharedBase = off;
    }
    __syncthreads();

    int run[8];
#pragma unroll
    for (int e = 0; e < 8; e++) {
        int pw = (wid == 0) ? 0 : warpsum[wid - 1][e];
        run[e] = sExpBase[e] + pw + (incl[e] - lc[e]);
    }
#pragma unroll
    for (int j = 0; j < 16; j++) {
        int e = eids[j];
        int pos = run[e]++;
        g_srcTok[pos] = (base + j) >> 1;
        g_slot[base + j] = pos;
    }
    for (int e = 0; e < 8; e++) {
        int s = sExpBase[e] + sExpCnt[e], en = sExpBase[e + 1];
        for (int p = s + tid; p < en; p += 1024) g_srcTok[p] = -1;
    }
    int sb = sExpBase[8];
    for (int t = tid; t < T_TOK; t += 1024) g_srcTok[sb + t] = t;
}

// ---------------- 3) fused GEMM1+3 + SwiGLU -> h (bf16 hi/lo) ----------------
// block 128(M) x 64(N) x Kc32, 256 thr, 8 warps (4m x 2n of 32x32), dual B (W1,W3)
#define PAE 40    // A pitch elems (80B)
#define PBE 72    // B pitch elems (144B)
// smem: AH 2x10240 @0, AL @20480, B1H 2x4608 @40960, B1L @50176, B3H @59392, B3L @68608
#define SMEM_G13 77824

__global__ __launch_bounds__(256, 2) void gemm13_swiglu(
    const float* __restrict__ b1, const float* __restrict__ b3,
    const float* __restrict__ sb1, const float* __restrict__ sb3)
{
    int tileId = blockIdx.y;
    if (tileId >= g_nTiles) return;
    extern __shared__ char sm[];
    uint32_t smb = smem_u32(sm);
    int tid = threadIdx.x, lane = tid & 31, warp = tid >> 5;
    int e = g_tileExpert[tileId];
    int rowBase = tileId << 7;
    int n0 = blockIdx.x << 6;

    const __nv_bfloat16* W1h = g_wh + (size_t)e * 1048576;
    const __nv_bfloat16* W1l = g_wl + (size_t)e * 1048576;
    const __nv_bfloat16* W3h = g_wh + (size_t)(9 + e) * 1048576;
    const __nv_bfloat16* W3l = g_wl + (size_t)(9 + e) * 1048576;
    const float* bi1 = (e < N_EXP) ? (b1 + e * 1024) : sb1;
    const float* bi3 = (e < N_EXP) ? (b3 + e * 1024) : sb3;

    // A loader: 128 rows x 2 planes; thread -> (plane=tid>>7, row=tid&127), 64B each
    int aplane = tid >> 7, arow = tid & 127;
    int tokA = g_srcTok[rowBase + arow];
    uint32_t aSz = (tokA >= 0) ? 16u : 0u;
    const __nv_bfloat16* aSrc =
        (aplane ? g_xl : g_xh) + (size_t)max(tokA, 0) * 1024;
    uint32_t aDst = smb + aplane * 20480 + arow * 80;

    // B loader: mat=tid>>7 (0:W1,1:W3), plane=(tid>>6)&1, row=(tid&63)>>1, seg=tid&1
    int bmat = tid >> 7, bplane = (tid >> 6) & 1, brow = (tid & 63) >> 1, bseg = tid & 1;
    const __nv_bfloat16* bSrc =
        (bmat ? (bplane ? W3l : W3h) : (bplane ? W1l : W1h))
        + (size_t)brow * 1024 + n0 + bseg * 32;
    uint32_t bDst = smb + 40960 + (bmat * 2 + bplane) * 9216 + brow * 144 + bseg * 64;

    auto issue = [&](int c) {
        int s = c & 1;
        const __nv_bfloat16* ap = aSrc + c * 32;
        uint32_t da = aDst + s * 10240;
#pragma unroll
        for (int q = 0; q < 4; q++) cpa16(da + q * 16, ap + q * 8, aSz);
        const __nv_bfloat16* bp = bSrc + (size_t)c * 32 * 1024;
        uint32_t db = bDst + s * 4608;
#pragma unroll
        for (int q = 0; q < 4; q++) cpa16(db + q * 16, bp + q * 8, 16u);
        CP_COMMIT();
    };

    float acc1[2][4][4], acc3[2][4][4];
#pragma unroll
    for (int m = 0; m < 2; m++)
#pragma unroll
        for (int n = 0; n < 4; n++)
#pragma unroll
            for (int j = 0; j < 4; j++) { acc1[m][n][j] = 0.f; acc3[m][n][j] = 0.f; }

    int warpM = (warp >> 1) * 32, warpN = (warp & 1) * 32;
    int lr = lane & 15, lcol = (lane >> 4) * 8;

    issue(0);
    for (int c = 0; c < 32; c++) {
        CP_WAIT0();
        __syncthreads();
        if (c + 1 < 32) issue(c + 1);
        int s = c & 1;
        uint32_t AHs = smb + s * 10240, ALs = smb + 20480 + s * 10240;
        uint32_t B1Hs = smb + 40960 + s * 4608, B1Ls = smb + 50176 + s * 4608;
        uint32_t B3Hs = smb + 59392 + s * 4608, B3Ls = smb + 68608 + s * 4608;
#pragma unroll
        for (int ks = 0; ks < 2; ks++) {
            uint32_t ah[2][4], al[2][4];
#pragma unroll
            for (int m = 0; m < 2; m++) {
                uint32_t o = (uint32_t)((warpM + m * 16 + lr) * PAE + ks * 16 + lcol) * 2;
                ldsm4(ah[m], AHs + o);
                ldsm4(al[m], ALs + o);
            }
#pragma unroll
            for (int np = 0; np < 2; np++) {
                uint32_t o = (uint32_t)((ks * 16 + lr) * PBE + warpN + np * 16 + lcol) * 2;
                uint32_t bh[4], bl[4];
                ldsm4t(bh, B1Hs + o);
                ldsm4t(bl, B1Ls + o);
#pragma unroll
                for (int m = 0; m < 2; m++) {
                    mma16816(acc1[m][2 * np],     ah[m], bh);
                    mma16816(acc1[m][2 * np],     ah[m], bl);
                    mma16816(acc1[m][2 * np],     al[m], bh);
                    mma16816(acc1[m][2 * np + 1], ah[m], bh + 2);
                    mma16816(acc1[m][2 * np + 1], ah[m], bl + 2);
                    mma16816(acc1[m][2 * np + 1], al[m], bh + 2);
                }
                ldsm4t(bh, B3Hs + o);
                ldsm4t(bl, B3Ls + o);
#pragma unroll
                for (int m = 0; m < 2; m++) {
                    mma16816(acc3[m][2 * np],     ah[m], bh);
                    mma16816(acc3[m][2 * np],     ah[m], bl);
                    mma16816(acc3[m][2 * np],     al[m], bh);
                    mma16816(acc3[m][2 * np + 1], ah[m], bh + 2);
                    mma16816(acc3[m][2 * np + 1], ah[m], bl + 2);
                    mma16816(acc3[m][2 * np + 1], al[m], bh + 2);
                }
            }
        }
    }

    // epilogue: SwiGLU, split to bf16 hi/lo, store h planes
    int g = lane >> 2, cc = (lane & 3) * 2;
#pragma unroll
    for (int m = 0; m < 2; m++) {
        int r0 = rowBase + warpM + m * 16 + g;
#pragma unroll
        for (int n = 0; n < 4; n++) {
            int col = n0 + warpN + n * 8 + cc;
            float b1v0 = bi1[col], b1v1 = bi1[col + 1];
            float b3v0 = bi3[col], b3v1 = bi3[col + 1];
#pragma unroll
            for (int hrow = 0; hrow < 2; hrow++) {
                int row = r0 + hrow * 8;
                float gv0 = acc1[m][n][2 * hrow]     + b1v0;
                float gv1 = acc1[m][n][2 * hrow + 1] + b1v1;
                float uv0 = acc3[m][n][2 * hrow]     + b3v0;
                float uv1 = acc3[m][n][2 * hrow + 1] + b3v1;
                float h0 = gv0 / (1.f + __expf(-gv0)) * uv0;
                float h1 = gv1 / (1.f + __expf(-gv1)) * uv1;
                size_t o = (size_t)row * 1024 + col;
                stHiLo2(&g_hh[o], &g_hl[o], h0, h1);
            }
        }
    }
}

// ---------------- 4) GEMM2: C2 = H @ W2 + b2 ----------------
// block 128(M) x 128(N) x Kc32, 256 thr, 8 warps (4m x 2n of 32x64)
#define PB2E 136  // B pitch elems (272B)
// smem: AH 2x10240 @0, AL @20480, BH 2x8704 @40960, BL @58368 -> 75776
#define SMEM_G2 75776

__global__ __launch_bounds__(256, 2) void gemm2_k(
    const float* __restrict__ b2, const float* __restrict__ sb2)
{
    int tileId = blockIdx.y;
    if (tileId >= g_nTiles) return;
    extern __shared__ char sm[];
    uint32_t smb = smem_u32(sm);
    int tid = threadIdx.x, lane = tid & 31, warp = tid >> 5;
    int e = g_tileExpert[tileId];
    int rowBase = tileId << 7;
    int n0 = blockIdx.x << 7;

    const __nv_bfloat16* Wh = g_wh + (size_t)(18 + e) * 1048576;
    const __nv_bfloat16* Wl = g_wl + (size_t)(18 + e) * 1048576;
    const float* bi = (e < N_EXP) ? (b2 + e * 1024) : sb2;

    int aplane = tid >> 7, arow = tid & 127;
    const __nv_bfloat16* aSrc =
        (aplane ? g_hl : g_hh) + (size_t)(rowBase + arow) * 1024;
    uint32_t aDst = smb + aplane * 20480 + arow * 80;

    int bplane = tid >> 7, brow = (tid & 127) >> 2, bseg = tid & 3;
    const __nv_bfloat16* bSrc = (bplane ? Wl : Wh) + (size_t)brow * 1024 + n0 + bseg * 32;
    uint32_t bDst = smb + 40960 + bplane * 17408 + brow * 272 + bseg * 64;

    auto issue = [&](int c) {
        int s = c & 1;
        const __nv_bfloat16* ap = aSrc + c * 32;
        uint32_t da = aDst + s * 10240;
#pragma unroll
        for (int q = 0; q < 4; q++) cpa16(da + q * 16, ap + q * 8, 16u);
        const __nv_bfloat16* bp = bSrc + (size_t)c * 32 * 1024;
        uint32_t db = bDst + s * 8704;
#pragma unroll
        for (int q = 0; q < 4; q++) cpa16(db + q * 16, bp + q * 8, 16u);
        CP_COMMIT();
    };

    float acc[2][8][4];
#pragma unroll
    for (int m = 0; m < 2; m++)
#pragma unroll
        for (int n = 0; n < 8; n++)
#pragma unroll
            for (int j = 0; j < 4; j++) acc[m][n][j] = 0.f;

    int warpM = (warp >> 1) * 32, warpN = (warp & 1) * 64;
    int lr = lane & 15, lcol = (lane >> 4) * 8;

    issue(0);
    for (int c = 0; c < 32; c++) {
        CP_WAIT0();
        __syncthreads();
        if (c + 1 < 32) issue(c + 1);
        int s = c & 1;
        uint32_t AHs = smb + s * 10240, ALs = smb + 20480 + s * 10240;
        uint32_t BHs = smb + 40960 + s * 8704, BLs = smb + 58368 + s * 8704;
#pragma unroll
        for (int ks = 0; ks < 2; ks++) {
            uint32_t ah[2][4], al[2][4];
#pragma unroll
            for (int m = 0; m < 2; m++) {
                uint32_t o = (uint32_t)((warpM + m * 16 + lr) * PAE + ks * 16 + lcol) * 2;
                ldsm4(ah[m], AHs + o);
                ldsm4(al[m], ALs + o);
            }
#pragma unroll
            for (int np = 0; np < 4; np++) {
                uint32_t o = (uint32_t)((ks * 16 + lr) * PB2E + warpN + np * 16 + lcol) * 2;
                uint32_t bh[4], bl[4];
                ldsm4t(bh, BHs + o);
                ldsm4t(bl, BLs + o);
#pragma unroll
                for (int m = 0; m < 2; m++) {
                    mma16816(acc[m][2 * np],     ah[m], bh);
                    mma16816(acc[m][2 * np],     ah[m], bl);
                    mma16816(acc[m][2 * np],     al[m], bh);
                    mma16816(acc[m][2 * np + 1], ah[m], bh + 2);
                    mma16816(acc[m][2 * np + 1], ah[m], bl + 2);
                    mma16816(acc[m][2 * np + 1], al[m], bh + 2);
                }
            }
        }
    }

    int g = lane >> 2, cc = (lane & 3) * 2;
#pragma unroll
    for (int m = 0; m < 2; m++) {
        int r0 = rowBase + warpM + m * 16 + g;
        float* C0 = g_c2 + (size_t)r0 * 1024;
        float* C1 = C0 + 8 * 1024;
#pragma unroll
        for (int n = 0; n < 8; n++) {
            int col = n0 + warpN + n * 8 + cc;
            float bb0 = bi[col], bb1 = bi[col + 1];
            *(float2*)&C0[col] = make_float2(acc[m][n][0] + bb0, acc[m][n][1] + bb1);
            *(float2*)&C1[col] = make_float2(acc[m][n][2] + bb0, acc[m][n][3] + bb1);
        }
    }
}

// ---------------- 5) combine ----------------
__global__ void combine_kernel(float* __restrict__ out) {
    int t = blockIdx.x;
    int d4 = threadIdx.x;
    int s0 = g_slot[2 * t], s1 = g_slot[2 * t + 1];
    float w0 = g_wgt[2 * t], w1 = g_wgt[2 * t + 1];
    int sh = g_sharedBase + t;
    float4 c0 = *((const float4*)(g_c2 + (size_t)s0 * D_MODEL) + d4);
    float4 c1 = *((const float4*)(g_c2 + (size_t)s1 * D_MODEL) + d4);
    float4 cs = *((const float4*)(g_c2 + (size_t)sh * D_MODEL) + d4);
    float4 r;
    r.x = fmaf(w0, c0.x, fmaf(w1, c1.x, cs.x));
    r.y = fmaf(w0, c0.y, fmaf(w1, c1.y, cs.y));
    r.z = fmaf(w0, c0.z, fmaf(w1, c1.z, cs.z));
    r.w = fmaf(w0, c0.w, fmaf(w1, c1.w, cs.w));
    *((float4*)(out + (size_t)t * D_MODEL) + d4) = r;
}

// ---------------- launch ----------------
extern "C" void kernel_launch(void* const* d_in, const int* in_sizes, int n_in,
                              void* d_out, int out_size) {
    const float* x   = (const float*)d_in[0];
    const float* gw  = (const float*)d_in[1];
    const float* w1  = (const float*)d_in[2];
    const float* b1  = (const float*)d_in[3];
    const float* w2  = (const float*)d_in[4];
    const float* b2  = (const float*)d_in[5];
    const float* w3  = (const float*)d_in[6];
    const float* b3  = (const float*)d_in[7];
    const float* sw1 = (const float*)d_in[8];
    const float* sb1 = (const float*)d_in[9];
    const float* sw2 = (const float*)d_in[10];
    const float* sb2 = (const float*)d_in[11];
    const float* sw3 = (const float*)d_in[12];
    const float* sb3 = (const float*)d_in[13];
    float* out = (float*)d_out;

    cudaFuncSetAttribute(gemm13_swiglu, cudaFuncAttributeMaxDynamicSharedMemorySize, SMEM_G13);
    cudaFuncSetAttribute(gemm2_k,       cudaFuncAttributeMaxDynamicSharedMemorySize, SMEM_G2);

    prep_w<<<dim3(1024, 27), 256>>>(w1, w3, w2, sw1, sw3, sw2);
    prep_x<<<T_TOK, 256>>>(x);
    gate_kernel<<<T_TOK / 4, 128>>>(x, gw);
    route_build<<<1, 1024>>>();
    gemm13_swiglu<<<dim3(16, MAX_TILES), 256, SMEM_G13>>>(b1, b3, sb1, sb3);
    gemm2_k<<<dim3(8, MAX_TILES), 256, SMEM_G2>>>(b2, sb2);
    combine_kernel<<<T_TOK, 256>>>(out);
}